// round 1
// baseline (speedup 1.0000x reference)
#include <cuda_runtime.h>
#include <cuda_bf16.h>

// Problem dims
#define BB 4
#define SS 512
#define EE 512
#define UU 256

// Scratch (allocation-free rule: __device__ globals)
__device__ float g_K[BB * SS * UU];   // key_pre + b1   (2 MB)
__device__ float g_Q[BB * SS * UU];   // qry_pre        (2 MB)
__device__ float g_S[BB * SS * SS];   // scores -> softmax probs in place (4 MB)

__device__ __forceinline__ float tanh_ap(float x) {
    float y; asm("tanh.approx.f32 %0, %1;" : "=f"(y) : "f"(x)); return y;
}
__device__ __forceinline__ float ex2_ap(float x) {
    float y; asm("ex2.approx.f32 %0, %1;" : "=f"(y) : "f"(x)); return y;
}

// ---------------------------------------------------------------------------
// Generic 64x64 tile SGEMM (NN, row-major), BK=16, 256 threads, 4x4/thread.
// M,N multiples of 64 via grid; K multiple of 16. Optional per-column bias.
// ---------------------------------------------------------------------------
__device__ __forceinline__ void sgemm_tile(
    const float* __restrict__ A, const float* __restrict__ B,
    float* __restrict__ C, const float* __restrict__ bias,
    int K, int lda, int ldb, int ldc)
{
    __shared__ float As[16][64];   // A^T tile
    __shared__ float Bs[16][64];

    const int tid = threadIdx.x;
    const int tx = tid & 15;        // N micro
    const int ty = tid >> 4;        // M micro

    // load mappings
    const int ar = tid >> 2;              // 0..63 (M row within tile)
    const int ac = (tid & 3) * 4;         // 0..12 (K col, float4)
    const int br = tid >> 4;              // 0..15 (K row)
    const int bc = (tid & 15) * 4;        // 0..60 (N col, float4)

    const float* Ap = A + (size_t)(blockIdx.y * 64 + ar) * lda + ac;
    const float* Bp = B + (size_t)br * ldb + blockIdx.x * 64 + bc;

    float acc[4][4] = {};

    for (int k0 = 0; k0 < K; k0 += 16) {
        float4 a = *(const float4*)Ap;          Ap += 16;
        float4 bv = *(const float4*)Bp;         Bp += (size_t)16 * ldb;
        As[ac + 0][ar] = a.x;
        As[ac + 1][ar] = a.y;
        As[ac + 2][ar] = a.z;
        As[ac + 3][ar] = a.w;
        *(float4*)&Bs[br][bc] = bv;
        __syncthreads();
#pragma unroll
        for (int kk = 0; kk < 16; kk++) {
            float4 av = *(const float4*)&As[kk][ty * 4];
            float4 bw = *(const float4*)&Bs[kk][tx * 4];
            acc[0][0] += av.x * bw.x; acc[0][1] += av.x * bw.y;
            acc[0][2] += av.x * bw.z; acc[0][3] += av.x * bw.w;
            acc[1][0] += av.y * bw.x; acc[1][1] += av.y * bw.y;
            acc[1][2] += av.y * bw.z; acc[1][3] += av.y * bw.w;
            acc[2][0] += av.z * bw.x; acc[2][1] += av.z * bw.y;
            acc[2][2] += av.z * bw.z; acc[2][3] += av.z * bw.w;
            acc[3][0] += av.w * bw.x; acc[3][1] += av.w * bw.y;
            acc[3][2] += av.w * bw.z; acc[3][3] += av.w * bw.w;
        }
        __syncthreads();
    }

    const int row0 = blockIdx.y * 64 + ty * 4;
    const int col0 = blockIdx.x * 64 + tx * 4;
    float4 bb = make_float4(0.f, 0.f, 0.f, 0.f);
    if (bias) bb = *(const float4*)(bias + col0);
#pragma unroll
    for (int i = 0; i < 4; i++) {
        float4 o;
        o.x = acc[i][0] + bb.x;
        o.y = acc[i][1] + bb.y;
        o.z = acc[i][2] + bb.z;
        o.w = acc[i][3] + bb.w;
        *(float4*)&C[(size_t)(row0 + i) * ldc + col0] = o;
    }
}

// Stage 1: K = h1 @ w[:E] + b1 ; Q = h2 @ w[E:]   (z selects)
// grid (256/64=4, 2048/64=32, 2), block 256
__global__ void qk_gemm(const float* __restrict__ h1, const float* __restrict__ h2,
                        const float* __restrict__ w, const float* __restrict__ b1)
{
    const int z = blockIdx.z;
    const float* A = z ? h2 : h1;
    const float* Bm = w + (size_t)z * EE * UU;
    float* C = z ? g_Q : g_K;
    const float* bias = z ? nullptr : b1;   // fold b1 into key_pre
    sgemm_tile(A, Bm, C, bias, EE, EE, UU, UU);
}

// Stage 2: scores[b,i,j] = sum_u v[u]*tanh(Q[b,i,u]+K[b,j,u]) + b2
// tile 32(i) x 32(j), 256 threads, U chunked by 128 (32 float4).
// grid (16 jt, 16 it, 4 b)
__global__ void scores_kernel(const float* __restrict__ v, const float* __restrict__ b2)
{
    __shared__ float4 q4[32][32];   // [i][u4]
    __shared__ float4 k4[32][33];   // padded to kill 32-way conflicts
    __shared__ float4 v4s[32];

    const int b  = blockIdx.z;
    const int it = blockIdx.y;
    const int jt = blockIdx.x;
    const int tid = threadIdx.x;
    const int jl = tid & 31;        // local j (lane)
    const int ib = tid >> 5;        // local i base (0..7)

    const float* Qb = g_Q + ((size_t)(b * SS + it * 32)) * UU;
    const float* Kb = g_K + ((size_t)(b * SS + jt * 32)) * UU;

    float acc[4] = {0.f, 0.f, 0.f, 0.f};

    for (int uc = 0; uc < 2; uc++) {
        const int base = uc * 32;   // float4 offset within row
        for (int t = tid; t < 32 * 32; t += 256) {
            const int r = t >> 5, c = t & 31;
            q4[r][c] = ((const float4*)(Qb + (size_t)r * UU))[base + c];
            k4[r][c] = ((const float4*)(Kb + (size_t)r * UU))[base + c];
        }
        if (tid < 32) v4s[tid] = ((const float4*)v)[base + tid];
        __syncthreads();

#pragma unroll 4
        for (int c = 0; c < 32; c++) {
            const float4 kv = k4[jl][c];
            const float4 vv = v4s[c];
#pragma unroll
            for (int r = 0; r < 4; r++) {
                const float4 qv = q4[ib + 8 * r][c];   // broadcast within warp
                acc[r] += vv.x * tanh_ap(qv.x + kv.x);
                acc[r] += vv.y * tanh_ap(qv.y + kv.y);
                acc[r] += vv.z * tanh_ap(qv.z + kv.z);
                acc[r] += vv.w * tanh_ap(qv.w + kv.w);
            }
        }
        __syncthreads();
    }

    const float bb = b2[0];
#pragma unroll
    for (int r = 0; r < 4; r++) {
        const int i = it * 32 + ib + 8 * r;
        g_S[((size_t)(b * SS + i)) * SS + jt * 32 + jl] = acc[r] + bb;
    }
}

// Stage 3: in-place row softmax over j (rows of 512). grid 2048, block 256.
__global__ void softmax_kernel()
{
    const int row = blockIdx.x;
    float* p = g_S + (size_t)row * SS;
    const int tid = threadIdx.x;

    float v0 = p[tid];
    float v1 = p[tid + 256];
    float m = fmaxf(v0, v1);
#pragma unroll
    for (int o = 16; o > 0; o >>= 1) m = fmaxf(m, __shfl_xor_sync(0xffffffffu, m, o));
    __shared__ float sm[8];
    __shared__ float ssum[8];
    if ((tid & 31) == 0) sm[tid >> 5] = m;
    __syncthreads();
    float bm = sm[0];
#pragma unroll
    for (int i = 1; i < 8; i++) bm = fmaxf(bm, sm[i]);

    const float L2E = 1.4426950408889634f;
    float e0 = ex2_ap((v0 - bm) * L2E);
    float e1 = ex2_ap((v1 - bm) * L2E);
    float s = e0 + e1;
#pragma unroll
    for (int o = 16; o > 0; o >>= 1) s += __shfl_xor_sync(0xffffffffu, s, o);
    if ((tid & 31) == 0) ssum[tid >> 5] = s;
    __syncthreads();
    float bs = 0.f;
#pragma unroll
    for (int i = 0; i < 8; i++) bs += ssum[i];

    const float inv = 1.0f / bs;
    p[tid]       = e0 * inv;
    p[tid + 256] = e1 * inv;
}

// Stage 4: out[b] = P[b] @ h1[b]   (512x512 @ 512x512), grid (8,8,4)
__global__ void pv_gemm(const float* __restrict__ h1, float* __restrict__ out)
{
    const int b = blockIdx.z;
    const float* P = g_S + (size_t)b * SS * SS;
    const float* Bm = h1 + (size_t)b * SS * EE;
    float* C = out + (size_t)b * SS * EE;
    sgemm_tile(P, Bm, C, nullptr, SS, SS, EE, EE);
}

extern "C" void kernel_launch(void* const* d_in, const int* in_sizes, int n_in,
                              void* d_out, int out_size)
{
    const float* h1 = (const float*)d_in[0];
    const float* h2 = (const float*)d_in[1];
    const float* w  = (const float*)d_in[2];
    const float* b1 = (const float*)d_in[3];
    const float* v  = (const float*)d_in[4];
    const float* b2 = (const float*)d_in[5];
    float* out = (float*)d_out;

    dim3 gA(UU / 64, (BB * SS) / 64, 2);     // (4, 32, 2)
    qk_gemm<<<gA, 256>>>(h1, h2, w, b1);

    dim3 gB(SS / 32, SS / 32, BB);           // (16, 16, 4)
    scores_kernel<<<gB, 256>>>(v, b2);

    softmax_kernel<<<BB * SS, 256>>>();      // 2048 rows

    dim3 gD(EE / 64, SS / 64, BB);           // (8, 8, 4)
    pv_gemm<<<gD, 256>>>(h1, out);
}